// round 5
// baseline (speedup 1.0000x reference)
#include <cuda_runtime.h>
#include <cuda_bf16.h>

// MixingBlock restructured:
//   M[b] = scale * Wq @ (slot[b]@Wk)^T   [180 x 32] per batch
//   dots[b,r,:] = x[b,r,:] @ M[b] ; w = softmax(dots); s = w @ slot[b]
// All fp32, packed f32x2 FMA (Blackwell FFMA2).
// Phase 3: warp tile 16r x 64c, lane = 4r x 8c; w via 4-way-distinct broadcast
// LDS (1 wf), v via direct LDG.128 from L1-resident slot (no staging, no syncs).

#define BB 4
#define RR 8192
#define SS 32
#define IN_DIM 180
#define SLOT_DIM 1536
#define ATT_DIM 1536
#define KSPLIT 8                  // gemm1 split over slot_dim reduction
#define KC (SLOT_DIM / KSPLIT)    // 192
#define ASPLIT 4                  // gemm2 split over att_dim reduction
#define AC (ATT_DIM / ASPLIT)     // 384
#define TILE_R 64

typedef unsigned long long u64;

__device__ __forceinline__ u64 fma2(u64 a, u64 b, u64 c) {
    u64 d;
    asm("fma.rn.f32x2 %0, %1, %2, %3;" : "=l"(d) : "l"(a), "l"(b), "l"(c));
    return d;
}
__device__ __forceinline__ u64 pk2(float v) {
    u64 r;
    asm("mov.b64 %0, {%1, %1};" : "=l"(r) : "r"(__float_as_uint(v)));
    return r;
}

// Scratch
__device__ float g_kpart[KSPLIT * BB * ATT_DIM * SS];  // [p][b][a][s]
__device__ float g_ksum[BB * ATT_DIM * SS];            // [b][a][s]
__device__ float g_Mpart[ASPLIT * BB * IN_DIM * SS];   // [p2][b][i][s]

// ---------------------------------------------------------------------------
// GEMM1: g_kpart[p][b][a][s] = sum_{j in chunk p} slot[b][s][j] * Wk[j][a]
// Grid (12, 4, 8) = 384 blocks, 256 threads, f32x2 microtile 4r x 4c.
// ---------------------------------------------------------------------------
__global__ __launch_bounds__(256) void gemm1_kernel(const float* __restrict__ slot,
                                                    const float* __restrict__ Wk) {
    __shared__ float As[32 * 36];   // [s][k], stride 36
    __shared__ float Bs[32 * 128];  // [k][c]
    int t = threadIdx.x;
    int warp = t >> 5, lane = t & 31;
    int a0 = blockIdx.x * 128;
    int b  = blockIdx.y;
    int p  = blockIdx.z;
    int j_base = p * KC;

    u64 acc[4][2] = {};
    for (int jc = 0; jc < KC / 32; jc++) {
        int j0 = j_base + jc * 32;
        {   // stage A: 32 s x 32 j
            int s_l = t >> 3, k4 = (t & 7) << 2;
            float4 v = *reinterpret_cast<const float4*>(
                &slot[(size_t)(b * SS + s_l) * SLOT_DIM + j0 + k4]);
            *reinterpret_cast<float4*>(&As[s_l * 36 + k4]) = v;
        }
        {   // stage B: 32 j x 128 a
            int k = t >> 3, cb = (t & 7) << 2;
            const float* src = &Wk[(size_t)(j0 + k) * ATT_DIM + a0];
            #pragma unroll
            for (int cc = 0; cc < 4; cc++) {
                int c = cb + cc * 32;
                *reinterpret_cast<float4*>(&Bs[k * 128 + c]) =
                    *reinterpret_cast<const float4*>(&src[c]);
            }
        }
        __syncthreads();
        #pragma unroll 8
        for (int k = 0; k < 32; k++) {
            ulonglong2 bv = *reinterpret_cast<const ulonglong2*>(&Bs[k * 128 + lane * 4]);
            #pragma unroll
            for (int ri = 0; ri < 4; ri++) {
                u64 a2 = pk2(As[(4 * warp + ri) * 36 + k]);
                acc[ri][0] = fma2(a2, bv.x, acc[ri][0]);
                acc[ri][1] = fma2(a2, bv.y, acc[ri][1]);
            }
        }
        __syncthreads();
    }
    float* dst = &g_kpart[((size_t)(p * BB + b) * ATT_DIM + a0) * SS];
    #pragma unroll
    for (int ri = 0; ri < 4; ri++) {
        #pragma unroll
        for (int cj = 0; cj < 2; cj++) {
            float lo = __uint_as_float((unsigned)(acc[ri][cj] & 0xffffffffu));
            float hi = __uint_as_float((unsigned)(acc[ri][cj] >> 32));
            dst[(lane * 4 + 2 * cj + 0) * SS + 4 * warp + ri] = lo;
            dst[(lane * 4 + 2 * cj + 1) * SS + 4 * warp + ri] = hi;
        }
    }
}

// ---------------------------------------------------------------------------
// Reduce: g_ksum = sum_p g_kpart
// ---------------------------------------------------------------------------
__global__ __launch_bounds__(256) void reducek_kernel() {
    int idx = blockIdx.x * 256 + threadIdx.x;  // float4 index over 49152
    const float4* src = reinterpret_cast<const float4*>(g_kpart);
    float4 a = src[idx];
    #pragma unroll
    for (int p = 1; p < KSPLIT; p++) {
        float4 v = src[(size_t)p * (BB * ATT_DIM * SS / 4) + idx];
        a.x += v.x; a.y += v.y; a.z += v.z; a.w += v.w;
    }
    reinterpret_cast<float4*>(g_ksum)[idx] = a;
}

// ---------------------------------------------------------------------------
// GEMM2: g_Mpart[p2][b][i][s] = sum_{a in chunk p2} Wq[i][a] * g_ksum[b][a][s]
// Grid (23, 4, 4), 256 threads; warp owns one i, lanes own s.
// ---------------------------------------------------------------------------
__global__ __launch_bounds__(256) void gemm2_kernel(const float* __restrict__ Wq) {
    __shared__ float ks[64 * 32];
    int t = threadIdx.x;
    int warp = t >> 5, lane = t & 31;
    int b = blockIdx.y, p2 = blockIdx.z;
    int i = blockIdx.x * 8 + warp;
    const float* kp = &g_ksum[(size_t)b * ATT_DIM * SS];
    int a_lo = p2 * AC;
    float acc = 0.f;
    for (int a0 = a_lo; a0 < a_lo + AC; a0 += 64) {
        __syncthreads();
        #pragma unroll
        for (int v = 0; v < 2; v++) {
            int lin = (t + v * 256) * 4;
            *reinterpret_cast<float4*>(&ks[lin]) =
                *reinterpret_cast<const float4*>(&kp[(size_t)a0 * SS + lin]);
        }
        __syncthreads();
        if (i < IN_DIM) {
            const float* wr = &Wq[(size_t)i * ATT_DIM + a0];
            #pragma unroll
            for (int aa = 0; aa < 64; aa += 4) {
                float4 w4 = *reinterpret_cast<const float4*>(&wr[aa]);
                acc += w4.x * ks[(aa + 0) * 32 + lane];
                acc += w4.y * ks[(aa + 1) * 32 + lane];
                acc += w4.z * ks[(aa + 2) * 32 + lane];
                acc += w4.w * ks[(aa + 3) * 32 + lane];
            }
        }
    }
    if (i < IN_DIM)
        g_Mpart[((size_t)(p2 * BB + b) * IN_DIM + i) * SS + lane] = acc;
}

// ---------------------------------------------------------------------------
// Fused: dots = x@M -> softmax -> s = w@slot.  64 rows/block, 256 thr, 3 blk/SM.
// Static smem (47616 B):
//   [0, 16384)      u64 w2t[32][64]   packed (w,w), transposed [s][r]
//   [16384, 39424)  float Ms[180][32]      (dead after phase 1)
//   [39424, 47616)  float dots[64][32]     (dead after phase 2)
// ---------------------------------------------------------------------------
__global__ __launch_bounds__(256, 3) void fused_kernel(const float* __restrict__ x,
                                                       const float* __restrict__ slot,
                                                       float* __restrict__ out_s,
                                                       float* __restrict__ out_w) {
    __shared__ __align__(16) char smraw[47616];
    u64*   w2t    = reinterpret_cast<u64*>(smraw);            // [s][64]
    float* Ms     = reinterpret_cast<float*>(smraw + 16384);  // [i][32]
    float* dots_s = reinterpret_cast<float*>(smraw + 39424);  // [r][32]

    int t = threadIdx.x;
    int warp = t >> 5, lane = t & 31;
    int r0 = blockIdx.x * TILE_R;
    int b  = blockIdx.y;
    const float scale = rsqrtf((float)ATT_DIM);

    // Load M[b] = scale * sum_{p2} Mpart
    for (int idx = t; idx < IN_DIM * SS; idx += 256) {
        float v = 0.f;
        #pragma unroll
        for (int p2 = 0; p2 < ASPLIT; p2++)
            v += g_Mpart[(size_t)(p2 * BB + b) * IN_DIM * SS + idx];
        Ms[idx] = v * scale;
    }
    __syncthreads();

    // phase 1: dots; thread owns 1 row x 8 s (4 threads share a row -> x LDG broadcast)
    {
        int sg = (t & 3) * 8;
        int r  = t >> 2;
        const float* xrow = &x[(size_t)(b * RR + r0 + r) * IN_DIM];
        u64 d2[4] = {0ull, 0ull, 0ull, 0ull};
        #pragma unroll 3
        for (int i4 = 0; i4 < IN_DIM / 4; i4++) {
            float4 xv = *reinterpret_cast<const float4*>(&xrow[i4 * 4]);
            const float* xc = reinterpret_cast<const float*>(&xv);
            #pragma unroll
            for (int c = 0; c < 4; c++) {
                int i = i4 * 4 + c;
                ulonglong2 m01 = *reinterpret_cast<const ulonglong2*>(&Ms[i * SS + sg]);
                ulonglong2 m23 = *reinterpret_cast<const ulonglong2*>(&Ms[i * SS + sg + 4]);
                u64 xp = pk2(xc[c]);
                d2[0] = fma2(xp, m01.x, d2[0]);
                d2[1] = fma2(xp, m01.y, d2[1]);
                d2[2] = fma2(xp, m23.x, d2[2]);
                d2[3] = fma2(xp, m23.y, d2[3]);
            }
        }
        ulonglong2 o0; o0.x = d2[0]; o0.y = d2[1];
        ulonglong2 o1; o1.x = d2[2]; o1.y = d2[3];
        *reinterpret_cast<ulonglong2*>(&dots_s[r * SS + sg]) = o0;
        *reinterpret_cast<ulonglong2*>(&dots_s[r * SS + sg + 4]) = o1;
    }
    __syncthreads();

    // phase 2: softmax; thread owns 1 row x 8 s, reduce over 4-lane groups.
    {
        int r = t >> 2;
        int sg = (t & 3) * 8;
        float v[8];
        float4 a0 = *reinterpret_cast<const float4*>(&dots_s[r * SS + sg]);
        float4 a1 = *reinterpret_cast<const float4*>(&dots_s[r * SS + sg + 4]);
        v[0] = a0.x; v[1] = a0.y; v[2] = a0.z; v[3] = a0.w;
        v[4] = a1.x; v[5] = a1.y; v[6] = a1.z; v[7] = a1.w;
        float mx = v[0];
        #pragma unroll
        for (int k = 1; k < 8; k++) mx = fmaxf(mx, v[k]);
        mx = fmaxf(mx, __shfl_xor_sync(0xffffffffu, mx, 1));
        mx = fmaxf(mx, __shfl_xor_sync(0xffffffffu, mx, 2));
        float sum = 0.f;
        #pragma unroll
        for (int k = 0; k < 8; k++) { v[k] = __expf(v[k] - mx); sum += v[k]; }
        sum += __shfl_xor_sync(0xffffffffu, sum, 1);
        sum += __shfl_xor_sync(0xffffffffu, sum, 2);
        float inv = 1.0f / sum;
        #pragma unroll
        for (int k = 0; k < 8; k++) v[k] *= inv;
        float* wp = &out_w[(size_t)(b * RR + r0 + r) * SS + sg];
        *reinterpret_cast<float4*>(&wp[0]) = make_float4(v[0], v[1], v[2], v[3]);
        *reinterpret_cast<float4*>(&wp[4]) = make_float4(v[4], v[5], v[6], v[7]);
        #pragma unroll
        for (int k = 0; k < 8; k++)
            w2t[(sg + k) * TILE_R + r] = pk2(v[k]);
    }
    __syncthreads();

    // phase 3: s = w @ slot.  96 tiles of 16r x 64c; warp does 12.
    // lane: rg = lane>>3 (4 rows), cg = lane&7 (8 cols). No smem staging/syncs.
    {
        int rg = lane >> 3, cg = lane & 7;
        const float* slotb = &slot[(size_t)b * SS * SLOT_DIM];
        for (int i = warp; i < 96; i += 8) {
            int rb = i & 3;          // row band (16 rows)
            int cb = i >> 2;         // col band (64 cols)
            int rloc = rb * 16 + rg * 4;          // local row of first of 4
            int c0   = cb * 64 + cg * 8;          // first of 8 cols
            const float* vsrc = slotb + c0;
            const u64*   wsrc = &w2t[rloc];       // + s*64 per step
            u64 acc[4][4] = {};
            #pragma unroll 8
            for (int s = 0; s < SS; s++) {
                ulonglong2 v0 = *reinterpret_cast<const ulonglong2*>(&vsrc[(size_t)s * SLOT_DIM]);
                ulonglong2 v1 = *reinterpret_cast<const ulonglong2*>(&vsrc[(size_t)s * SLOT_DIM + 4]);
                ulonglong2 w01 = *reinterpret_cast<const ulonglong2*>(&wsrc[s * TILE_R]);
                ulonglong2 w23 = *reinterpret_cast<const ulonglong2*>(&wsrc[s * TILE_R + 2]);
                acc[0][0] = fma2(w01.x, v0.x, acc[0][0]);
                acc[0][1] = fma2(w01.x, v0.y, acc[0][1]);
                acc[0][2] = fma2(w01.x, v1.x, acc[0][2]);
                acc[0][3] = fma2(w01.x, v1.y, acc[0][3]);
                acc[1][0] = fma2(w01.y, v0.x, acc[1][0]);
                acc[1][1] = fma2(w01.y, v0.y, acc[1][1]);
                acc[1][2] = fma2(w01.y, v1.x, acc[1][2]);
                acc[1][3] = fma2(w01.y, v1.y, acc[1][3]);
                acc[2][0] = fma2(w23.x, v0.x, acc[2][0]);
                acc[2][1] = fma2(w23.x, v0.y, acc[2][1]);
                acc[2][2] = fma2(w23.x, v1.x, acc[2][2]);
                acc[2][3] = fma2(w23.x, v1.y, acc[2][3]);
                acc[3][0] = fma2(w23.y, v0.x, acc[3][0]);
                acc[3][1] = fma2(w23.y, v0.y, acc[3][1]);
                acc[3][2] = fma2(w23.y, v1.x, acc[3][2]);
                acc[3][3] = fma2(w23.y, v1.y, acc[3][3]);
            }
            #pragma unroll
            for (int rr = 0; rr < 4; rr++) {
                float* orow = &out_s[(size_t)(b * RR + r0 + rloc + rr) * SLOT_DIM + c0];
                ulonglong2 o0; o0.x = acc[rr][0]; o0.y = acc[rr][1];
                ulonglong2 o1; o1.x = acc[rr][2]; o1.y = acc[rr][3];
                *reinterpret_cast<ulonglong2*>(&orow[0]) = o0;
                *reinterpret_cast<ulonglong2*>(&orow[4]) = o1;
            }
        }
    }
}

// ---------------------------------------------------------------------------
extern "C" void kernel_launch(void* const* d_in, const int* in_sizes, int n_in,
                              void* d_out, int out_size) {
    const float* x    = (const float*)d_in[0];  // [4, 8192, 180]
    const float* slot = (const float*)d_in[1];  // [4, 32, 1536]
    const float* Wq   = (const float*)d_in[2];  // [180, 1536]
    const float* Wk   = (const float*)d_in[3];  // [1536, 1536]
    float* out_s = (float*)d_out;                        // [4, 8192, 1536]
    float* out_w = out_s + (size_t)BB * RR * ATT_DIM;    // [4, 8192, 32]

    gemm1_kernel<<<dim3(ATT_DIM / 128, BB, KSPLIT), 256>>>(slot, Wk);
    reducek_kernel<<<(BB * ATT_DIM * SS / 4) / 256, 256>>>();
    gemm2_kernel<<<dim3((IN_DIM + 7) / 8, BB, ASPLIT), 256>>>(Wq);
    fused_kernel<<<dim3(RR / TILE_R, BB), 256>>>(x, slot, out_s, out_w);
}

// round 6
// speedup vs baseline: 1.0081x; 1.0081x over previous
#include <cuda_runtime.h>
#include <cuda_bf16.h>

// MixingBlock restructured:
//   M[b] = scale * Wq @ (slot[b]@Wk)^T   [180 x 32] per batch
//   dots[b,r,:] = x[b,r,:] @ M[b] ; w = softmax(dots); s = w @ slot[b]
// All fp32, packed f32x2 FMA (Blackwell FFMA2).
// Phase 3: warp tile 16r x 64c, lane = 4r x 8c; w via 4-way-distinct broadcast
// LDS (1 wf), v via direct LDG.128 from L1-resident slot (no staging, no syncs).

#define BB 4
#define RR 8192
#define SS 32
#define IN_DIM 180
#define SLOT_DIM 1536
#define ATT_DIM 1536
#define KSPLIT 8                  // gemm1 split over slot_dim reduction
#define KC (SLOT_DIM / KSPLIT)    // 192
#define ASPLIT 4                  // gemm2 split over att_dim reduction
#define AC (ATT_DIM / ASPLIT)     // 384
#define TILE_R 64

typedef unsigned long long u64;

__device__ __forceinline__ u64 fma2(u64 a, u64 b, u64 c) {
    u64 d;
    asm("fma.rn.f32x2 %0, %1, %2, %3;" : "=l"(d) : "l"(a), "l"(b), "l"(c));
    return d;
}
__device__ __forceinline__ u64 pk2(float v) {
    u64 r;
    asm("mov.b64 %0, {%1, %1};" : "=l"(r) : "r"(__float_as_uint(v)));
    return r;
}

// Scratch
__device__ float g_kpart[KSPLIT * BB * ATT_DIM * SS];  // [p][b][a][s]
__device__ float g_ksum[BB * ATT_DIM * SS];            // [b][a][s]
__device__ float g_Mpart[ASPLIT * BB * IN_DIM * SS];   // [p2][b][i][s]

// ---------------------------------------------------------------------------
// GEMM1: g_kpart[p][b][a][s] = sum_{j in chunk p} slot[b][s][j] * Wk[j][a]
// Grid (12, 4, 8) = 384 blocks, 256 threads, f32x2 microtile 4r x 4c.
// ---------------------------------------------------------------------------
__global__ __launch_bounds__(256) void gemm1_kernel(const float* __restrict__ slot,
                                                    const float* __restrict__ Wk) {
    __shared__ float As[32 * 36];   // [s][k], stride 36
    __shared__ float Bs[32 * 128];  // [k][c]
    int t = threadIdx.x;
    int warp = t >> 5, lane = t & 31;
    int a0 = blockIdx.x * 128;
    int b  = blockIdx.y;
    int p  = blockIdx.z;
    int j_base = p * KC;

    u64 acc[4][2] = {};
    for (int jc = 0; jc < KC / 32; jc++) {
        int j0 = j_base + jc * 32;
        {   // stage A: 32 s x 32 j
            int s_l = t >> 3, k4 = (t & 7) << 2;
            float4 v = *reinterpret_cast<const float4*>(
                &slot[(size_t)(b * SS + s_l) * SLOT_DIM + j0 + k4]);
            *reinterpret_cast<float4*>(&As[s_l * 36 + k4]) = v;
        }
        {   // stage B: 32 j x 128 a
            int k = t >> 3, cb = (t & 7) << 2;
            const float* src = &Wk[(size_t)(j0 + k) * ATT_DIM + a0];
            #pragma unroll
            for (int cc = 0; cc < 4; cc++) {
                int c = cb + cc * 32;
                *reinterpret_cast<float4*>(&Bs[k * 128 + c]) =
                    *reinterpret_cast<const float4*>(&src[c]);
            }
        }
        __syncthreads();
        #pragma unroll 8
        for (int k = 0; k < 32; k++) {
            ulonglong2 bv = *reinterpret_cast<const ulonglong2*>(&Bs[k * 128 + lane * 4]);
            #pragma unroll
            for (int ri = 0; ri < 4; ri++) {
                u64 a2 = pk2(As[(4 * warp + ri) * 36 + k]);
                acc[ri][0] = fma2(a2, bv.x, acc[ri][0]);
                acc[ri][1] = fma2(a2, bv.y, acc[ri][1]);
            }
        }
        __syncthreads();
    }
    float* dst = &g_kpart[((size_t)(p * BB + b) * ATT_DIM + a0) * SS];
    #pragma unroll
    for (int ri = 0; ri < 4; ri++) {
        #pragma unroll
        for (int cj = 0; cj < 2; cj++) {
            float lo = __uint_as_float((unsigned)(acc[ri][cj] & 0xffffffffu));
            float hi = __uint_as_float((unsigned)(acc[ri][cj] >> 32));
            dst[(lane * 4 + 2 * cj + 0) * SS + 4 * warp + ri] = lo;
            dst[(lane * 4 + 2 * cj + 1) * SS + 4 * warp + ri] = hi;
        }
    }
}

// ---------------------------------------------------------------------------
// Reduce: g_ksum = sum_p g_kpart
// ---------------------------------------------------------------------------
__global__ __launch_bounds__(256) void reducek_kernel() {
    int idx = blockIdx.x * 256 + threadIdx.x;  // float4 index over 49152
    const float4* src = reinterpret_cast<const float4*>(g_kpart);
    float4 a = src[idx];
    #pragma unroll
    for (int p = 1; p < KSPLIT; p++) {
        float4 v = src[(size_t)p * (BB * ATT_DIM * SS / 4) + idx];
        a.x += v.x; a.y += v.y; a.z += v.z; a.w += v.w;
    }
    reinterpret_cast<float4*>(g_ksum)[idx] = a;
}

// ---------------------------------------------------------------------------
// GEMM2: g_Mpart[p2][b][i][s] = sum_{a in chunk p2} Wq[i][a] * g_ksum[b][a][s]
// Grid (23, 4, 4), 256 threads; warp owns one i, lanes own s.
// ---------------------------------------------------------------------------
__global__ __launch_bounds__(256) void gemm2_kernel(const float* __restrict__ Wq) {
    __shared__ float ks[64 * 32];
    int t = threadIdx.x;
    int warp = t >> 5, lane = t & 31;
    int b = blockIdx.y, p2 = blockIdx.z;
    int i = blockIdx.x * 8 + warp;
    const float* kp = &g_ksum[(size_t)b * ATT_DIM * SS];
    int a_lo = p2 * AC;
    float acc = 0.f;
    for (int a0 = a_lo; a0 < a_lo + AC; a0 += 64) {
        __syncthreads();
        #pragma unroll
        for (int v = 0; v < 2; v++) {
            int lin = (t + v * 256) * 4;
            *reinterpret_cast<float4*>(&ks[lin]) =
                *reinterpret_cast<const float4*>(&kp[(size_t)a0 * SS + lin]);
        }
        __syncthreads();
        if (i < IN_DIM) {
            const float* wr = &Wq[(size_t)i * ATT_DIM + a0];
            #pragma unroll
            for (int aa = 0; aa < 64; aa += 4) {
                float4 w4 = *reinterpret_cast<const float4*>(&wr[aa]);
                acc += w4.x * ks[(aa + 0) * 32 + lane];
                acc += w4.y * ks[(aa + 1) * 32 + lane];
                acc += w4.z * ks[(aa + 2) * 32 + lane];
                acc += w4.w * ks[(aa + 3) * 32 + lane];
            }
        }
    }
    if (i < IN_DIM)
        g_Mpart[((size_t)(p2 * BB + b) * IN_DIM + i) * SS + lane] = acc;
}

// ---------------------------------------------------------------------------
// Fused: dots = x@M -> softmax -> s = w@slot.  64 rows/block, 256 thr, 3 blk/SM.
// Static smem (47616 B):
//   [0, 16384)      u64 w2t[32][64]   packed (w,w), transposed [s][r]
//   [16384, 39424)  float Ms[180][32]      (dead after phase 1)
//   [39424, 47616)  float dots[64][32]     (dead after phase 2)
// ---------------------------------------------------------------------------
__global__ __launch_bounds__(256, 3) void fused_kernel(const float* __restrict__ x,
                                                       const float* __restrict__ slot,
                                                       float* __restrict__ out_s,
                                                       float* __restrict__ out_w) {
    __shared__ __align__(16) char smraw[47616];
    u64*   w2t    = reinterpret_cast<u64*>(smraw);            // [s][64]
    float* Ms     = reinterpret_cast<float*>(smraw + 16384);  // [i][32]
    float* dots_s = reinterpret_cast<float*>(smraw + 39424);  // [r][32]

    int t = threadIdx.x;
    int warp = t >> 5, lane = t & 31;
    int r0 = blockIdx.x * TILE_R;
    int b  = blockIdx.y;
    const float scale = rsqrtf((float)ATT_DIM);

    // Load M[b] = scale * sum_{p2} Mpart
    for (int idx = t; idx < IN_DIM * SS; idx += 256) {
        float v = 0.f;
        #pragma unroll
        for (int p2 = 0; p2 < ASPLIT; p2++)
            v += g_Mpart[(size_t)(p2 * BB + b) * IN_DIM * SS + idx];
        Ms[idx] = v * scale;
    }
    __syncthreads();

    // phase 1: dots; thread owns 1 row x 8 s (4 threads share a row -> x LDG broadcast)
    {
        int sg = (t & 3) * 8;
        int r  = t >> 2;
        const float* xrow = &x[(size_t)(b * RR + r0 + r) * IN_DIM];
        u64 d2[4] = {0ull, 0ull, 0ull, 0ull};
        #pragma unroll 3
        for (int i4 = 0; i4 < IN_DIM / 4; i4++) {
            float4 xv = *reinterpret_cast<const float4*>(&xrow[i4 * 4]);
            const float* xc = reinterpret_cast<const float*>(&xv);
            #pragma unroll
            for (int c = 0; c < 4; c++) {
                int i = i4 * 4 + c;
                ulonglong2 m01 = *reinterpret_cast<const ulonglong2*>(&Ms[i * SS + sg]);
                ulonglong2 m23 = *reinterpret_cast<const ulonglong2*>(&Ms[i * SS + sg + 4]);
                u64 xp = pk2(xc[c]);
                d2[0] = fma2(xp, m01.x, d2[0]);
                d2[1] = fma2(xp, m01.y, d2[1]);
                d2[2] = fma2(xp, m23.x, d2[2]);
                d2[3] = fma2(xp, m23.y, d2[3]);
            }
        }
        ulonglong2 o0; o0.x = d2[0]; o0.y = d2[1];
        ulonglong2 o1; o1.x = d2[2]; o1.y = d2[3];
        *reinterpret_cast<ulonglong2*>(&dots_s[r * SS + sg]) = o0;
        *reinterpret_cast<ulonglong2*>(&dots_s[r * SS + sg + 4]) = o1;
    }
    __syncthreads();

    // phase 2: softmax; thread owns 1 row x 8 s, reduce over 4-lane groups.
    {
        int r = t >> 2;
        int sg = (t & 3) * 8;
        float v[8];
        float4 a0 = *reinterpret_cast<const float4*>(&dots_s[r * SS + sg]);
        float4 a1 = *reinterpret_cast<const float4*>(&dots_s[r * SS + sg + 4]);
        v[0] = a0.x; v[1] = a0.y; v[2] = a0.z; v[3] = a0.w;
        v[4] = a1.x; v[5] = a1.y; v[6] = a1.z; v[7] = a1.w;
        float mx = v[0];
        #pragma unroll
        for (int k = 1; k < 8; k++) mx = fmaxf(mx, v[k]);
        mx = fmaxf(mx, __shfl_xor_sync(0xffffffffu, mx, 1));
        mx = fmaxf(mx, __shfl_xor_sync(0xffffffffu, mx, 2));
        float sum = 0.f;
        #pragma unroll
        for (int k = 0; k < 8; k++) { v[k] = __expf(v[k] - mx); sum += v[k]; }
        sum += __shfl_xor_sync(0xffffffffu, sum, 1);
        sum += __shfl_xor_sync(0xffffffffu, sum, 2);
        float inv = 1.0f / sum;
        #pragma unroll
        for (int k = 0; k < 8; k++) v[k] *= inv;
        float* wp = &out_w[(size_t)(b * RR + r0 + r) * SS + sg];
        *reinterpret_cast<float4*>(&wp[0]) = make_float4(v[0], v[1], v[2], v[3]);
        *reinterpret_cast<float4*>(&wp[4]) = make_float4(v[4], v[5], v[6], v[7]);
        #pragma unroll
        for (int k = 0; k < 8; k++)
            w2t[(sg + k) * TILE_R + r] = pk2(v[k]);
    }
    __syncthreads();

    // phase 3: s = w @ slot.  96 tiles of 16r x 64c; warp does 12.
    // lane: rg = lane>>3 (4 rows), cg = lane&7 (8 cols). No smem staging/syncs.
    {
        int rg = lane >> 3, cg = lane & 7;
        const float* slotb = &slot[(size_t)b * SS * SLOT_DIM];
        for (int i = warp; i < 96; i += 8) {
            int rb = i & 3;          // row band (16 rows)
            int cb = i >> 2;         // col band (64 cols)
            int rloc = rb * 16 + rg * 4;          // local row of first of 4
            int c0   = cb * 64 + cg * 8;          // first of 8 cols
            const float* vsrc = slotb + c0;
            const u64*   wsrc = &w2t[rloc];       // + s*64 per step
            u64 acc[4][4] = {};
            #pragma unroll 8
            for (int s = 0; s < SS; s++) {
                ulonglong2 v0 = *reinterpret_cast<const ulonglong2*>(&vsrc[(size_t)s * SLOT_DIM]);
                ulonglong2 v1 = *reinterpret_cast<const ulonglong2*>(&vsrc[(size_t)s * SLOT_DIM + 4]);
                ulonglong2 w01 = *reinterpret_cast<const ulonglong2*>(&wsrc[s * TILE_R]);
                ulonglong2 w23 = *reinterpret_cast<const ulonglong2*>(&wsrc[s * TILE_R + 2]);
                acc[0][0] = fma2(w01.x, v0.x, acc[0][0]);
                acc[0][1] = fma2(w01.x, v0.y, acc[0][1]);
                acc[0][2] = fma2(w01.x, v1.x, acc[0][2]);
                acc[0][3] = fma2(w01.x, v1.y, acc[0][3]);
                acc[1][0] = fma2(w01.y, v0.x, acc[1][0]);
                acc[1][1] = fma2(w01.y, v0.y, acc[1][1]);
                acc[1][2] = fma2(w01.y, v1.x, acc[1][2]);
                acc[1][3] = fma2(w01.y, v1.y, acc[1][3]);
                acc[2][0] = fma2(w23.x, v0.x, acc[2][0]);
                acc[2][1] = fma2(w23.x, v0.y, acc[2][1]);
                acc[2][2] = fma2(w23.x, v1.x, acc[2][2]);
                acc[2][3] = fma2(w23.x, v1.y, acc[2][3]);
                acc[3][0] = fma2(w23.y, v0.x, acc[3][0]);
                acc[3][1] = fma2(w23.y, v0.y, acc[3][1]);
                acc[3][2] = fma2(w23.y, v1.x, acc[3][2]);
                acc[3][3] = fma2(w23.y, v1.y, acc[3][3]);
            }
            #pragma unroll
            for (int rr = 0; rr < 4; rr++) {
                float* orow = &out_s[(size_t)(b * RR + r0 + rloc + rr) * SLOT_DIM + c0];
                ulonglong2 o0; o0.x = acc[rr][0]; o0.y = acc[rr][1];
                ulonglong2 o1; o1.x = acc[rr][2]; o1.y = acc[rr][3];
                *reinterpret_cast<ulonglong2*>(&orow[0]) = o0;
                *reinterpret_cast<ulonglong2*>(&orow[4]) = o1;
            }
        }
    }
}

// ---------------------------------------------------------------------------
extern "C" void kernel_launch(void* const* d_in, const int* in_sizes, int n_in,
                              void* d_out, int out_size) {
    const float* x    = (const float*)d_in[0];  // [4, 8192, 180]
    const float* slot = (const float*)d_in[1];  // [4, 32, 1536]
    const float* Wq   = (const float*)d_in[2];  // [180, 1536]
    const float* Wk   = (const float*)d_in[3];  // [1536, 1536]
    float* out_s = (float*)d_out;                        // [4, 8192, 1536]
    float* out_w = out_s + (size_t)BB * RR * ATT_DIM;    // [4, 8192, 32]

    gemm1_kernel<<<dim3(ATT_DIM / 128, BB, KSPLIT), 256>>>(slot, Wk);
    reducek_kernel<<<(BB * ATT_DIM * SS / 4) / 256, 256>>>();
    gemm2_kernel<<<dim3((IN_DIM + 7) / 8, BB, ASPLIT), 256>>>(Wq);
    fused_kernel<<<dim3(RR / TILE_R, BB), 256>>>(x, slot, out_s, out_w);
}

// round 8
// speedup vs baseline: 1.2379x; 1.2280x over previous
#include <cuda_runtime.h>
#include <cuda_bf16.h>
#include <cstdint>

// MixingBlock:
//   M[b] = scale * Wq @ (slot[b]@Wk)^T  [180x32];  dots = x@M; w = softmax(dots);
//   s = w @ slot[b]  via mma.sync bf16-split (wh*vh + wh*vl + wl*vh), fp32 accum.
#define BB 4
#define RR 8192
#define SS 32
#define IN_DIM 180
#define SLOT_DIM 1536
#define ATT_DIM 1536
#define KSPLIT 8
#define KC (SLOT_DIM / KSPLIT)    // 192
#define ASPLIT 4
#define AC (ATT_DIM / ASPLIT)     // 384
#define TILE_R 128

typedef unsigned long long u64;

__device__ __forceinline__ u64 fma2(u64 a, u64 b, u64 c) {
    u64 d;
    asm("fma.rn.f32x2 %0, %1, %2, %3;" : "=l"(d) : "l"(a), "l"(b), "l"(c));
    return d;
}
__device__ __forceinline__ u64 pk2(float v) {
    u64 r;
    asm("mov.b64 %0, {%1, %1};" : "=l"(r) : "r"(__float_as_uint(v)));
    return r;
}
// pack two f32 -> bf16x2 (lo in low half, hi in high half)
__device__ __forceinline__ uint32_t bfpack(float lo, float hi) {
    uint32_t r;
    asm("cvt.rn.bf16x2.f32 %0, %1, %2;" : "=r"(r) : "f"(hi), "f"(lo));
    return r;
}
// D(16x8,f32) += A(16x16 bf16 row) * B(16x8 bf16 col)
__device__ __forceinline__ void mma16816(float* c, uint32_t a0, uint32_t a1,
                                         uint32_t a2, uint32_t a3,
                                         uint32_t b0, uint32_t b1) {
    asm volatile(
        "mma.sync.aligned.m16n8k16.row.col.f32.bf16.bf16.f32 "
        "{%0,%1,%2,%3}, {%4,%5,%6,%7}, {%8,%9}, {%0,%1,%2,%3};"
        : "+f"(c[0]), "+f"(c[1]), "+f"(c[2]), "+f"(c[3])
        : "r"(a0), "r"(a1), "r"(a2), "r"(a3), "r"(b0), "r"(b1));
}

// ---- scratch ---------------------------------------------------------------
__device__ float g_kpart[KSPLIT * BB * ATT_DIM * SS];
__device__ float g_ksum[BB * ATT_DIM * SS];
__device__ float g_Mpart[ASPLIT * BB * IN_DIM * SS];
// v bf16-split, fragment-group layout: per (b,d): 4 x uint4, group g holds
// slot-pairs {(2g,2g+1),(2g+8,2g+9),(2g+16,2g+17),(2g+24,2g+25)} as bf16x2.
__device__ uint4 g_vh[(size_t)BB * SLOT_DIM * 4];
__device__ uint4 g_vl[(size_t)BB * SLOT_DIM * 4];

// -----------------------------------------------------------------------------
// GEMM1 (proven): g_kpart[p][b][a][s] = sum_{j in chunk p} slot[b][s][j]*Wk[j][a]
// -----------------------------------------------------------------------------
__global__ __launch_bounds__(256) void gemm1_kernel(const float* __restrict__ slot,
                                                    const float* __restrict__ Wk) {
    __shared__ float As[32 * 36];
    __shared__ float Bs[32 * 128];
    int t = threadIdx.x;
    int warp = t >> 5, lane = t & 31;
    int a0 = blockIdx.x * 128;
    int b  = blockIdx.y;
    int p  = blockIdx.z;
    int j_base = p * KC;

    u64 acc[4][2] = {};
    for (int jc = 0; jc < KC / 32; jc++) {
        int j0 = j_base + jc * 32;
        {
            int s_l = t >> 3, k4 = (t & 7) << 2;
            float4 v = *reinterpret_cast<const float4*>(
                &slot[(size_t)(b * SS + s_l) * SLOT_DIM + j0 + k4]);
            *reinterpret_cast<float4*>(&As[s_l * 36 + k4]) = v;
        }
        {
            int k = t >> 3, cb = (t & 7) << 2;
            const float* src = &Wk[(size_t)(j0 + k) * ATT_DIM + a0];
            #pragma unroll
            for (int cc = 0; cc < 4; cc++) {
                int c = cb + cc * 32;
                *reinterpret_cast<float4*>(&Bs[k * 128 + c]) =
                    *reinterpret_cast<const float4*>(&src[c]);
            }
        }
        __syncthreads();
        #pragma unroll 8
        for (int k = 0; k < 32; k++) {
            ulonglong2 bv = *reinterpret_cast<const ulonglong2*>(&Bs[k * 128 + lane * 4]);
            #pragma unroll
            for (int ri = 0; ri < 4; ri++) {
                u64 a2 = pk2(As[(4 * warp + ri) * 36 + k]);
                acc[ri][0] = fma2(a2, bv.x, acc[ri][0]);
                acc[ri][1] = fma2(a2, bv.y, acc[ri][1]);
            }
        }
        __syncthreads();
    }
    float* dst = &g_kpart[((size_t)(p * BB + b) * ATT_DIM + a0) * SS];
    #pragma unroll
    for (int ri = 0; ri < 4; ri++)
        #pragma unroll
        for (int cj = 0; cj < 2; cj++) {
            float lo = __uint_as_float((unsigned)(acc[ri][cj] & 0xffffffffu));
            float hi = __uint_as_float((unsigned)(acc[ri][cj] >> 32));
            dst[(lane * 4 + 2 * cj + 0) * SS + 4 * warp + ri] = lo;
            dst[(lane * 4 + 2 * cj + 1) * SS + 4 * warp + ri] = hi;
        }
}

__global__ __launch_bounds__(256) void reducek_kernel() {
    int idx = blockIdx.x * 256 + threadIdx.x;
    const float4* src = reinterpret_cast<const float4*>(g_kpart);
    float4 a = src[idx];
    #pragma unroll
    for (int p = 1; p < KSPLIT; p++) {
        float4 v = src[(size_t)p * (BB * ATT_DIM * SS / 4) + idx];
        a.x += v.x; a.y += v.y; a.z += v.z; a.w += v.w;
    }
    reinterpret_cast<float4*>(g_ksum)[idx] = a;
}

__global__ __launch_bounds__(256) void gemm2_kernel(const float* __restrict__ Wq) {
    __shared__ float ks[64 * 32];
    int t = threadIdx.x;
    int warp = t >> 5, lane = t & 31;
    int b = blockIdx.y, p2 = blockIdx.z;
    int i = blockIdx.x * 8 + warp;
    const float* kp = &g_ksum[(size_t)b * ATT_DIM * SS];
    int a_lo = p2 * AC;
    float acc = 0.f;
    for (int a0 = a_lo; a0 < a_lo + AC; a0 += 64) {
        __syncthreads();
        #pragma unroll
        for (int v = 0; v < 2; v++) {
            int lin = (t + v * 256) * 4;
            *reinterpret_cast<float4*>(&ks[lin]) =
                *reinterpret_cast<const float4*>(&kp[(size_t)a0 * SS + lin]);
        }
        __syncthreads();
        if (i < IN_DIM) {
            const float* wr = &Wq[(size_t)i * ATT_DIM + a0];
            #pragma unroll
            for (int aa = 0; aa < 64; aa += 4) {
                float4 w4 = *reinterpret_cast<const float4*>(&wr[aa]);
                acc += w4.x * ks[(aa + 0) * 32 + lane];
                acc += w4.y * ks[(aa + 1) * 32 + lane];
                acc += w4.z * ks[(aa + 2) * 32 + lane];
                acc += w4.w * ks[(aa + 3) * 32 + lane];
            }
        }
    }
    if (i < IN_DIM)
        g_Mpart[((size_t)(p2 * BB + b) * IN_DIM + i) * SS + lane] = acc;
}

// -----------------------------------------------------------------------------
// vsplit: build g_vh / g_vl fragment groups. One thread per (b, d).
// -----------------------------------------------------------------------------
__global__ __launch_bounds__(256) void vsplit_kernel(const float* __restrict__ slot) {
    int idx = blockIdx.x * 256 + threadIdx.x;   // b*1536 + d
    int b = idx / SLOT_DIM, d = idx - b * SLOT_DIM;
    uint32_t ph[16], pl[16];
    #pragma unroll
    for (int j = 0; j < 16; j++) {
        float v0 = slot[(size_t)(b * SS + 2 * j + 0) * SLOT_DIM + d];
        float v1 = slot[(size_t)(b * SS + 2 * j + 1) * SLOT_DIM + d];
        __nv_bfloat16 h0 = __float2bfloat16(v0), h1 = __float2bfloat16(v1);
        ph[j] = (uint32_t)__bfloat16_as_ushort(h0) |
                ((uint32_t)__bfloat16_as_ushort(h1) << 16);
        pl[j] = bfpack(v0 - __bfloat162float(h0), v1 - __bfloat162float(h1));
    }
    uint4* oh = g_vh + (size_t)idx * 4;
    uint4* ol = g_vl + (size_t)idx * 4;
    #pragma unroll
    for (int g = 0; g < 4; g++) {
        oh[g] = make_uint4(ph[g], ph[g + 4], ph[g + 8], ph[g + 12]);
        ol[g] = make_uint4(pl[g], pl[g + 4], pl[g + 8], pl[g + 12]);
    }
}

// -----------------------------------------------------------------------------
// Fused: dots (FFMA2) -> softmax -> bf16-split mma.sync epilogue.
// 128 rows/block, 256 threads, 8 warps x 16 rows.
// smem: whs/wls = w tiles in A-fragment group layout; Ms = M[b] fp32.
// -----------------------------------------------------------------------------
__global__ __launch_bounds__(256) void fused_kernel(const float* __restrict__ x,
                                                    float* __restrict__ out_s,
                                                    float* __restrict__ out_w) {
    __shared__ uint4 whs[TILE_R * 4];     // 8 KB: [r][group g] = {pw[g],pw[g+4],pw[g+8],pw[g+12]}
    __shared__ uint4 wls[TILE_R * 4];     // 8 KB
    __shared__ float Ms[IN_DIM * SS];     // 23040 B

    int t = threadIdx.x;
    int warp = t >> 5, lane = t & 31;
    int r0 = blockIdx.x * TILE_R;
    int b  = blockIdx.y;
    const float scale = rsqrtf((float)ATT_DIM);

    // Load M[b] = scale * sum_p Mpart
    for (int idx = t; idx < IN_DIM * SS; idx += 256) {
        float v = 0.f;
        #pragma unroll
        for (int p2 = 0; p2 < ASPLIT; p2++)
            v += g_Mpart[(size_t)(p2 * BB + b) * IN_DIM * SS + idx];
        Ms[idx] = v * scale;
    }
    __syncthreads();

    // ---- phase 1+2: dots + softmax. thread = 1 row x 16 slots (2 threads/row).
    {
        int r  = t >> 1;          // 0..127
        int h  = t & 1;
        int sg = h * 16;
        const float* xrow = &x[(size_t)(b * RR + r0 + r) * IN_DIM];
        u64 d2[8] = {};
        #pragma unroll 3
        for (int i4 = 0; i4 < IN_DIM / 4; i4++) {
            float4 xv = *reinterpret_cast<const float4*>(&xrow[i4 * 4]);
            const float* xc = reinterpret_cast<const float*>(&xv);
            #pragma unroll
            for (int c = 0; c < 4; c++) {
                int i = 4 * i4 + c;
                const u64* m = reinterpret_cast<const u64*>(&Ms[i * SS + sg]);
                u64 xp = pk2(xc[c]);
                #pragma unroll
                for (int q = 0; q < 8; q++) d2[q] = fma2(xp, m[q], d2[q]);
            }
        }
        float v[16];
        #pragma unroll
        for (int q = 0; q < 8; q++) {
            v[2 * q]     = __uint_as_float((unsigned)(d2[q] & 0xffffffffu));
            v[2 * q + 1] = __uint_as_float((unsigned)(d2[q] >> 32));
        }
        float mx = v[0];
        #pragma unroll
        for (int k = 1; k < 16; k++) mx = fmaxf(mx, v[k]);
        mx = fmaxf(mx, __shfl_xor_sync(0xffffffffu, mx, 1));
        float sum = 0.f;
        #pragma unroll
        for (int k = 0; k < 16; k++) { v[k] = __expf(v[k] - mx); sum += v[k]; }
        sum += __shfl_xor_sync(0xffffffffu, sum, 1);
        float inv = 1.0f / sum;
        #pragma unroll
        for (int k = 0; k < 16; k++) v[k] *= inv;

        // out_w (exact fp32)
        float* wp = &out_w[(size_t)(b * RR + r0 + r) * SS + sg];
        #pragma unroll
        for (int q = 0; q < 4; q++)
            *reinterpret_cast<float4*>(&wp[4 * q]) =
                make_float4(v[4 * q], v[4 * q + 1], v[4 * q + 2], v[4 * q + 3]);

        // pack w -> bf16 split, store into fragment-group smem layout.
        // this thread owns slot-pairs pw[8h + j] = slots (16h+2j, 16h+2j+1).
        uint32_t ph[8], pl[8];
        #pragma unroll
        for (int j = 0; j < 8; j++) {
            float f0 = v[2 * j], f1 = v[2 * j + 1];
            __nv_bfloat16 h0 = __float2bfloat16(f0), h1 = __float2bfloat16(f1);
            ph[j] = (uint32_t)__bfloat16_as_ushort(h0) |
                    ((uint32_t)__bfloat16_as_ushort(h1) << 16);
            pl[j] = bfpack(f0 - __bfloat162float(h0), f1 - __bfloat162float(h1));
        }
        // group g uint4 = {pw[g], pw[g+4], pw[g+8], pw[g+12]}:
        //   h=0 thread supplies .x=pw[g], .y=pw[g+4]  (pw idx g, g+4 = local j)
        //   h=1 thread supplies .z=pw[g+8], .w=pw[g+12] (local j = g, g+4)
        char* wh8 = reinterpret_cast<char*>(whs) + r * 64 + h * 8;
        char* wl8 = reinterpret_cast<char*>(wls) + r * 64 + h * 8;
        #pragma unroll
        for (int g = 0; g < 4; g++) {
            *reinterpret_cast<uint2*>(wh8 + g * 16) = make_uint2(ph[g], ph[g + 4]);
            *reinterpret_cast<uint2*>(wl8 + g * 16) = make_uint2(pl[g], pl[g + 4]);
        }
    }
    __syncthreads();

    // ---- phase 3: s = w @ slot via mma.sync, warp owns 16 rows x all 1536 d.
    {
        int rr = lane >> 2;          // 0..7  (A/C row, B n-index)
        int c2 = lane & 3;           // fragment k-group
        int rbase = warp * 16;
        // A fragments (reused across all d-tiles):
        uint4 HL = whs[(rbase + rr) * 4 + c2];
        uint4 HH = whs[(rbase + rr + 8) * 4 + c2];
        uint4 LL = wls[(rbase + rr) * 4 + c2];
        uint4 LH = wls[(rbase + rr + 8) * 4 + c2];

        const uint4* vhp = g_vh + ((size_t)b * SLOT_DIM + rr) * 4 + c2;
        const uint4* vlp = g_vl + ((size_t)b * SLOT_DIM + rr) * 4 + c2;
        float* orow0 = &out_s[(size_t)(b * RR + r0 + rbase + rr) * SLOT_DIM];
        float* orow1 = orow0 + (size_t)8 * SLOT_DIM;

        #pragma unroll 2
        for (int n0 = 0; n0 < SLOT_DIM / 8; n0++) {
            uint4 BH = vhp[(size_t)n0 * 32];   // 8 d-rows * 4 groups
            uint4 BL = vlp[(size_t)n0 * 32];
            float c[4] = {0.f, 0.f, 0.f, 0.f};
            mma16816(c, HL.x, HH.x, HL.y, HH.y, BH.x, BH.y);  // wh*vh k0
            mma16816(c, HL.z, HH.z, HL.w, HH.w, BH.z, BH.w);  // wh*vh k1
            mma16816(c, HL.x, HH.x, HL.y, HH.y, BL.x, BL.y);  // wh*vl k0
            mma16816(c, HL.z, HH.z, HL.w, HH.w, BL.z, BL.w);  // wh*vl k1
            mma16816(c, LL.x, LH.x, LL.y, LH.y, BH.x, BH.y);  // wl*vh k0
            mma16816(c, LL.z, LH.z, LL.w, LH.w, BH.z, BH.w);  // wl*vh k1
            int d = n0 * 8 + 2 * c2;
            *reinterpret_cast<float2*>(&orow0[d]) = make_float2(c[0], c[1]);
            *reinterpret_cast<float2*>(&orow1[d]) = make_float2(c[2], c[3]);
        }
    }
}

// -----------------------------------------------------------------------------
extern "C" void kernel_launch(void* const* d_in, const int* in_sizes, int n_in,
                              void* d_out, int out_size) {
    const float* x    = (const float*)d_in[0];  // [4, 8192, 180]
    const float* slot = (const float*)d_in[1];  // [4, 32, 1536]
    const float* Wq   = (const float*)d_in[2];  // [180, 1536]
    const float* Wk   = (const float*)d_in[3];  // [1536, 1536]
    float* out_s = (float*)d_out;                        // [4, 8192, 1536]
    float* out_w = out_s + (size_t)BB * RR * ATT_DIM;    // [4, 8192, 32]

    vsplit_kernel<<<(BB * SLOT_DIM) / 256, 256>>>(slot);
    gemm1_kernel<<<dim3(ATT_DIM / 128, BB, KSPLIT), 256>>>(slot, Wk);
    reducek_kernel<<<(BB * ATT_DIM * SS / 4) / 256, 256>>>();
    gemm2_kernel<<<dim3((IN_DIM + 7) / 8, BB, ASPLIT), 256>>>(Wq);
    fused_kernel<<<dim3(RR / TILE_R, BB), 256>>>(x, out_s, out_w);
}

// round 9
// speedup vs baseline: 1.5752x; 1.2725x over previous
#include <cuda_runtime.h>
#include <cuda_bf16.h>
#include <cstdint>

// MixingBlock:
//   M[b] = scale * Wq @ (slot[b]@Wk)^T  [180x32];  dots = x@M; w = softmax(dots);
//   s = w @ slot[b]  via mma.sync bf16-split (wh*vh + wh*vl + wl*vh), fp32 accum.
#define BB 4
#define RR 8192
#define SS 32
#define IN_DIM 180
#define SLOT_DIM 1536
#define ATT_DIM 1536
#define KSPLIT 8
#define KC (SLOT_DIM / KSPLIT)    // 192
#define ASPLIT 4
#define AC (ATT_DIM / ASPLIT)     // 384
#define TILE_R 64
#define NDB 48                    // 32-d blocks per batch

typedef unsigned long long u64;

__device__ __forceinline__ u64 fma2(u64 a, u64 b, u64 c) {
    u64 d;
    asm("fma.rn.f32x2 %0, %1, %2, %3;" : "=l"(d) : "l"(a), "l"(b), "l"(c));
    return d;
}
__device__ __forceinline__ u64 pk2(float v) {
    u64 r;
    asm("mov.b64 %0, {%1, %1};" : "=l"(r) : "r"(__float_as_uint(v)));
    return r;
}
__device__ __forceinline__ uint32_t bfpack(float lo, float hi) {
    uint32_t r;
    asm("cvt.rn.bf16x2.f32 %0, %1, %2;" : "=r"(r) : "f"(hi), "f"(lo));
    return r;
}
// D(16x8,f32) += A(16x16 bf16 row) * B(16x8 bf16 col)
__device__ __forceinline__ void mma16816(float* c, uint32_t a0, uint32_t a1,
                                         uint32_t a2, uint32_t a3,
                                         uint32_t b0, uint32_t b1) {
    asm volatile(
        "mma.sync.aligned.m16n8k16.row.col.f32.bf16.bf16.f32 "
        "{%0,%1,%2,%3}, {%4,%5,%6,%7}, {%8,%9}, {%0,%1,%2,%3};"
        : "+f"(c[0]), "+f"(c[1]), "+f"(c[2]), "+f"(c[3])
        : "r"(a0), "r"(a1), "r"(a2), "r"(a3), "r"(b0), "r"(b1));
}

// ---- scratch ---------------------------------------------------------------
__device__ float g_kpart[KSPLIT * BB * ATT_DIM * SS];
__device__ float g_ksum[BB * ATT_DIM * SS];
__device__ float g_Mpart[ASPLIT * BB * IN_DIM * SS];
// v bf16-split in d-permuted fragment layout:
//   per (b, dblock): 128 uint4 indexed [j(4)][rr(8)][c2(4)];
//   (j, rr) slot holds global d = dblock*32 + 8*(rr>>1) + 2*j + (rr&1);
//   uint4 group c2 = {p[c2], p[c2+4], p[c2+8], p[c2+12]}, p[m] = slots(2m,2m+1).
__device__ uint4 g_vh[(size_t)BB * NDB * 128];
__device__ uint4 g_vl[(size_t)BB * NDB * 128];

// -----------------------------------------------------------------------------
// GEMM1 (proven): g_kpart[p][b][a][s] = sum_{j in chunk p} slot[b][s][j]*Wk[j][a]
// -----------------------------------------------------------------------------
__global__ __launch_bounds__(256) void gemm1_kernel(const float* __restrict__ slot,
                                                    const float* __restrict__ Wk) {
    __shared__ float As[32 * 36];
    __shared__ float Bs[32 * 128];
    int t = threadIdx.x;
    int warp = t >> 5, lane = t & 31;
    int a0 = blockIdx.x * 128;
    int b  = blockIdx.y;
    int p  = blockIdx.z;
    int j_base = p * KC;

    u64 acc[4][2] = {};
    for (int jc = 0; jc < KC / 32; jc++) {
        int j0 = j_base + jc * 32;
        {
            int s_l = t >> 3, k4 = (t & 7) << 2;
            float4 v = *reinterpret_cast<const float4*>(
                &slot[(size_t)(b * SS + s_l) * SLOT_DIM + j0 + k4]);
            *reinterpret_cast<float4*>(&As[s_l * 36 + k4]) = v;
        }
        {
            int k = t >> 3, cb = (t & 7) << 2;
            const float* src = &Wk[(size_t)(j0 + k) * ATT_DIM + a0];
            #pragma unroll
            for (int cc = 0; cc < 4; cc++) {
                int c = cb + cc * 32;
                *reinterpret_cast<float4*>(&Bs[k * 128 + c]) =
                    *reinterpret_cast<const float4*>(&src[c]);
            }
        }
        __syncthreads();
        #pragma unroll 8
        for (int k = 0; k < 32; k++) {
            ulonglong2 bv = *reinterpret_cast<const ulonglong2*>(&Bs[k * 128 + lane * 4]);
            #pragma unroll
            for (int ri = 0; ri < 4; ri++) {
                u64 a2 = pk2(As[(4 * warp + ri) * 36 + k]);
                acc[ri][0] = fma2(a2, bv.x, acc[ri][0]);
                acc[ri][1] = fma2(a2, bv.y, acc[ri][1]);
            }
        }
        __syncthreads();
    }
    float* dst = &g_kpart[((size_t)(p * BB + b) * ATT_DIM + a0) * SS];
    #pragma unroll
    for (int ri = 0; ri < 4; ri++)
        #pragma unroll
        for (int cj = 0; cj < 2; cj++) {
            float lo = __uint_as_float((unsigned)(acc[ri][cj] & 0xffffffffu));
            float hi = __uint_as_float((unsigned)(acc[ri][cj] >> 32));
            dst[(lane * 4 + 2 * cj + 0) * SS + 4 * warp + ri] = lo;
            dst[(lane * 4 + 2 * cj + 1) * SS + 4 * warp + ri] = hi;
        }
}

__global__ __launch_bounds__(256) void reducek_kernel() {
    int idx = blockIdx.x * 256 + threadIdx.x;
    const float4* src = reinterpret_cast<const float4*>(g_kpart);
    float4 a = src[idx];
    #pragma unroll
    for (int p = 1; p < KSPLIT; p++) {
        float4 v = src[(size_t)p * (BB * ATT_DIM * SS / 4) + idx];
        a.x += v.x; a.y += v.y; a.z += v.z; a.w += v.w;
    }
    reinterpret_cast<float4*>(g_ksum)[idx] = a;
}

// -----------------------------------------------------------------------------
// GEMM2 v2: one 48KB smem load + one sync (was 6 LDG->sync rounds, 17us).
// g_Mpart[p2][b][i][s] = sum_{a in chunk p2} Wq[i][a] * g_ksum[b][a][s]
// -----------------------------------------------------------------------------
__global__ __launch_bounds__(256) void gemm2_kernel(const float* __restrict__ Wq) {
    __shared__ float ks[AC * 32];   // 48KB exactly
    int t = threadIdx.x;
    int warp = t >> 5, lane = t & 31;
    int b = blockIdx.y, p2 = blockIdx.z;
    int i = blockIdx.x * 8 + warp;
    const float4* kp4 = reinterpret_cast<const float4*>(
        g_ksum + (size_t)b * ATT_DIM * SS + (size_t)p2 * AC * SS);
    #pragma unroll
    for (int u = 0; u < (AC * 32 / 4) / 256; u++)
        reinterpret_cast<float4*>(ks)[t + u * 256] = kp4[t + u * 256];
    __syncthreads();
    if (i < IN_DIM) {
        const float* wr = &Wq[(size_t)i * ATT_DIM + p2 * AC];
        float acc = 0.f;
        #pragma unroll 8
        for (int aa = 0; aa < AC; aa += 4) {
            float4 w4 = *reinterpret_cast<const float4*>(&wr[aa]);
            acc += w4.x * ks[(aa + 0) * 32 + lane];
            acc += w4.y * ks[(aa + 1) * 32 + lane];
            acc += w4.z * ks[(aa + 2) * 32 + lane];
            acc += w4.w * ks[(aa + 3) * 32 + lane];
        }
        g_Mpart[((size_t)(p2 * BB + b) * IN_DIM + i) * SS + lane] = acc;
    }
}

// -----------------------------------------------------------------------------
// vsplit: build d-permuted fragment tiles. One thread per (b, d).
// -----------------------------------------------------------------------------
__global__ __launch_bounds__(256) void vsplit_kernel(const float* __restrict__ slot) {
    int idx = blockIdx.x * 256 + threadIdx.x;   // b*1536 + d
    int b = idx / SLOT_DIM, d = idx - b * SLOT_DIM;
    uint32_t ph[16], pl[16];
    #pragma unroll
    for (int m = 0; m < 16; m++) {
        float v0 = slot[(size_t)(b * SS + 2 * m + 0) * SLOT_DIM + d];
        float v1 = slot[(size_t)(b * SS + 2 * m + 1) * SLOT_DIM + d];
        __nv_bfloat16 h0 = __float2bfloat16(v0), h1 = __float2bfloat16(v1);
        ph[m] = (uint32_t)__bfloat16_as_ushort(h0) |
                ((uint32_t)__bfloat16_as_ushort(h1) << 16);
        pl[m] = bfpack(v0 - __bfloat162float(h0), v1 - __bfloat162float(h1));
    }
    int dblock = d >> 5, l = d & 31;
    int aa = l >> 3, jj = (l & 7) >> 1, e = l & 1, rr = 2 * aa + e;
    size_t base = (size_t)(b * NDB + dblock) * 128 + jj * 32 + rr * 4;
    #pragma unroll
    for (int g = 0; g < 4; g++) {
        g_vh[base + g] = make_uint4(ph[g], ph[g + 4], ph[g + 8], ph[g + 12]);
        g_vl[base + g] = make_uint4(pl[g], pl[g + 4], pl[g + 8], pl[g + 12]);
    }
}

// -----------------------------------------------------------------------------
// Fused: dots (FFMA2) -> softmax (regs) -> mma.sync epilogue with B smem staging
// and d-permuted STG.128 stores. 64 rows/block, 8 warps = 4 row-groups x 2 d-halves.
// smem: whs/wls (A frags, 4KB each) + ubuf{ Ms 23040B | B-stage 16KB }.
// -----------------------------------------------------------------------------
__global__ __launch_bounds__(256, 3) void fused_kernel(const float* __restrict__ x,
                                                       float* __restrict__ out_s,
                                                       float* __restrict__ out_w) {
    __shared__ __align__(16) uint4 whs[TILE_R * 4];
    __shared__ __align__(16) uint4 wls[TILE_R * 4];
    __shared__ __align__(16) char ubuf[23040];
    float* Ms  = reinterpret_cast<float*>(ubuf);
    uint4* sVH = reinterpret_cast<uint4*>(ubuf);        // 512 uint4 (8KB)
    uint4* sVL = reinterpret_cast<uint4*>(ubuf) + 512;  // 512 uint4 (8KB)

    int t = threadIdx.x;
    int warp = t >> 5, lane = t & 31;
    int r0 = blockIdx.x * TILE_R;
    int b  = blockIdx.y;
    const float scale = rsqrtf((float)ATT_DIM);

    // Load M[b] = scale * sum_p Mpart
    for (int idx = t; idx < IN_DIM * SS; idx += 256) {
        float v = 0.f;
        #pragma unroll
        for (int p2 = 0; p2 < ASPLIT; p2++)
            v += g_Mpart[(size_t)(p2 * BB + b) * IN_DIM * SS + idx];
        Ms[idx] = v * scale;
    }
    __syncthreads();

    // ---- phase 1+2: thread = 1 row x 8 slots (4 threads/row); stay in regs.
    {
        int r  = t >> 2;
        int q  = t & 3;
        int sg = q * 8;
        const float* xrow = &x[(size_t)(b * RR + r0 + r) * IN_DIM];
        u64 d2[4] = {};
        #pragma unroll 3
        for (int i4 = 0; i4 < IN_DIM / 4; i4++) {
            float4 xv = *reinterpret_cast<const float4*>(&xrow[i4 * 4]);
            const float* xc = reinterpret_cast<const float*>(&xv);
            #pragma unroll
            for (int c = 0; c < 4; c++) {
                int i = 4 * i4 + c;
                ulonglong2 m01 = *reinterpret_cast<const ulonglong2*>(&Ms[i * SS + sg]);
                ulonglong2 m23 = *reinterpret_cast<const ulonglong2*>(&Ms[i * SS + sg + 4]);
                u64 xp = pk2(xc[c]);
                d2[0] = fma2(xp, m01.x, d2[0]);
                d2[1] = fma2(xp, m01.y, d2[1]);
                d2[2] = fma2(xp, m23.x, d2[2]);
                d2[3] = fma2(xp, m23.y, d2[3]);
            }
        }
        float v[8];
        #pragma unroll
        for (int qq = 0; qq < 4; qq++) {
            v[2 * qq]     = __uint_as_float((unsigned)(d2[qq] & 0xffffffffu));
            v[2 * qq + 1] = __uint_as_float((unsigned)(d2[qq] >> 32));
        }
        float mx = v[0];
        #pragma unroll
        for (int k = 1; k < 8; k++) mx = fmaxf(mx, v[k]);
        mx = fmaxf(mx, __shfl_xor_sync(0xffffffffu, mx, 1));
        mx = fmaxf(mx, __shfl_xor_sync(0xffffffffu, mx, 2));
        float sum = 0.f;
        #pragma unroll
        for (int k = 0; k < 8; k++) { v[k] = __expf(v[k] - mx); sum += v[k]; }
        sum += __shfl_xor_sync(0xffffffffu, sum, 1);
        sum += __shfl_xor_sync(0xffffffffu, sum, 2);
        float inv = 1.0f / sum;
        #pragma unroll
        for (int k = 0; k < 8; k++) v[k] *= inv;

        float* wp = &out_w[(size_t)(b * RR + r0 + r) * SS + sg];
        *reinterpret_cast<float4*>(&wp[0]) = make_float4(v[0], v[1], v[2], v[3]);
        *reinterpret_cast<float4*>(&wp[4]) = make_float4(v[4], v[5], v[6], v[7]);

        // pack into A-fragment group layout: thread q writes component q of
        // groups 0..3 for its row (pair m = 4q+i -> group i, component q).
        uint32_t* whp = reinterpret_cast<uint32_t*>(whs + r * 4);
        uint32_t* wlp = reinterpret_cast<uint32_t*>(wls + r * 4);
        #pragma unroll
        for (int i = 0; i < 4; i++) {
            float f0 = v[2 * i], f1 = v[2 * i + 1];
            __nv_bfloat16 h0 = __float2bfloat16(f0), h1 = __float2bfloat16(f1);
            uint32_t uh = (uint32_t)__bfloat16_as_ushort(h0) |
                          ((uint32_t)__bfloat16_as_ushort(h1) << 16);
            uint32_t ul = bfpack(f0 - __bfloat162float(h0),
                                 f1 - __bfloat162float(h1));
            whp[i * 4 + q] = uh;
            wlp[i * 4 + q] = ul;
        }
    }
    __syncthreads();

    // ---- phase 3: warp = (rg = row-group of 16, dh = d-half of 768).
    {
        int rg = warp & 3, dh = warp >> 2;
        int rr = lane >> 2, c2 = lane & 3;
        int rbase = rg * 16;
        uint4 HL = whs[(rbase + rr) * 4 + c2];
        uint4 HH = whs[(rbase + rr + 8) * 4 + c2];
        uint4 LL = wls[(rbase + rr) * 4 + c2];
        uint4 LH = wls[(rbase + rr + 8) * 4 + c2];

        for (int g = 0; g < 12; g++) {
            __syncthreads();
            {   // stage 4 dblocks (2 per d-half) = 16KB
                int u = t * 2;
                int s = u >> 7;
                int srcdb = (s >> 1) * 24 + 2 * g + (s & 1);
                const uint4* sh = g_vh + (size_t)(b * NDB + srcdb) * 128 + (u & 127);
                const uint4* sl = g_vl + (size_t)(b * NDB + srcdb) * 128 + (u & 127);
                sVH[u] = sh[0]; sVH[u + 1] = sh[1];
                sVL[u] = sl[0]; sVL[u + 1] = sl[1];
            }
            __syncthreads();
            #pragma unroll
            for (int lloc = 0; lloc < 2; lloc++) {
                int db = dh * 24 + 2 * g + lloc;
                const uint4* bh = &sVH[(dh * 2 + lloc) * 128 + rr * 4 + c2];
                const uint4* bl = &sVL[(dh * 2 + lloc) * 128 + rr * 4 + c2];
                float c[4][4] = {};
                #pragma unroll
                for (int j = 0; j < 4; j++) {
                    uint4 BH = bh[j * 32];
                    uint4 BL = bl[j * 32];
                    mma16816(c[j], HL.x, HH.x, HL.y, HH.y, BH.x, BH.y);
                    mma16816(c[j], HL.z, HH.z, HL.w, HH.w, BH.z, BH.w);
                    mma16816(c[j], HL.x, HH.x, HL.y, HH.y, BL.x, BL.y);
                    mma16816(c[j], HL.z, HH.z, HL.w, HH.w, BL.z, BL.w);
                    mma16816(c[j], LL.x, LH.x, LL.y, LH.y, BH.x, BH.y);
                    mma16816(c[j], LL.z, LH.z, LL.w, LH.w, BH.z, BH.w);
                }
                // lane holds 8 consecutive d (= dblock*32 + 8*c2 ..) per row.
                float* orow = &out_s[(size_t)(b * RR + r0 + rbase + rr) * SLOT_DIM
                                     + db * 32 + 8 * c2];
                *reinterpret_cast<float4*>(orow) =
                    make_float4(c[0][0], c[0][1], c[1][0], c[1][1]);
                *reinterpret_cast<float4*>(orow + 4) =
                    make_float4(c[2][0], c[2][1], c[3][0], c[3][1]);
                float* orow8 = orow + (size_t)8 * SLOT_DIM;
                *reinterpret_cast<float4*>(orow8) =
                    make_float4(c[0][2], c[0][3], c[1][2], c[1][3]);
                *reinterpret_cast<float4*>(orow8 + 4) =
                    make_float4(c[2][2], c[2][3], c[3][2], c[3][3]);
            }
        }
    }
}

// -----------------------------------------------------------------------------
extern "C" void kernel_launch(void* const* d_in, const int* in_sizes, int n_in,
                              void* d_out, int out_size) {
    const float* x    = (const float*)d_in[0];  // [4, 8192, 180]
    const float* slot = (const float*)d_in[1];  // [4, 32, 1536]
    const float* Wq   = (const float*)d_in[2];  // [180, 1536]
    const float* Wk   = (const float*)d_in[3];  // [1536, 1536]
    float* out_s = (float*)d_out;                        // [4, 8192, 1536]
    float* out_w = out_s + (size_t)BB * RR * ATT_DIM;    // [4, 8192, 32]

    vsplit_kernel<<<(BB * SLOT_DIM) / 256, 256>>>(slot);
    gemm1_kernel<<<dim3(ATT_DIM / 128, BB, KSPLIT), 256>>>(slot, Wk);
    reducek_kernel<<<(BB * ATT_DIM * SS / 4) / 256, 256>>>();
    gemm2_kernel<<<dim3((IN_DIM + 7) / 8, BB, ASPLIT), 256>>>(Wq);
    fused_kernel<<<dim3(RR / TILE_R, BB), 256>>>(x, out_s, out_w);
}